// round 13
// baseline (speedup 1.0000x reference)
#include <cuda_runtime.h>
#include <cstdint>

// StructAttentionLayer: B=16384, A=50, D=256, fp32. HBM-bound (873MB, read once).
// R13 = R12 (best: 123.4us — non-persistent, 1 tile/CTA, 52KB SMEM, 4 slots/SM,
// evict_first TMA, deferred-normalization softmax, chunk-overlapped wsum) with
// THREE asymmetric chunks (20/20/10 rows): A-wsum hides under B's stream,
// B-wsum hides under C's stream; exposed tail is only the 10-row chunk C.
//   q[a] = exp(leakyrelu(e[a])) (no max shift — validated rel_err ~3e-7),
//   out = (A/Σq) · Σ q[a]·attrs[a,:].

#define A_NUM 50
#define D_DIM 256
#define ALPHA 0.2f
#define ROWS_A 20
#define ROWS_B 20
#define ROWS_C 10
#define BASE_B 20
#define BASE_C 40
#define CHUNKA_BYTES (ROWS_A * D_DIM * 4)       // 20480
#define CHUNKB_BYTES (ROWS_B * D_DIM * 4)       // 20480
#define CHUNKC_BYTES (ROWS_C * D_DIM * 4)       // 10240
#define ENT_BYTES    (D_DIM * 4)                // 1024
#define TILE_BYTES   (A_NUM * D_DIM * 4)        // 51200
#define DYN_SMEM     (TILE_BYTES + ENT_BYTES)   // 52224

__global__ __launch_bounds__(256, 4)
void struct_attn_kernel(const float* __restrict__ attrs,
                        const float* __restrict__ ent,
                        const float* __restrict__ aa,
                        float* __restrict__ out)
{
    extern __shared__ __align__(128) float sm[];
    float* tile = sm;                          // tile[a*256 + d]
    float* ents = sm + A_NUM * D_DIM;          // ents[256]

    __shared__ float e_s[52];                  // unnormalized weights q[a]
    __shared__ __align__(8) unsigned long long mbar[4];  // [0]=ent,[1]=A,[2]=B,[3]=C

    const int b    = blockIdx.x;
    const int t    = threadIdx.x;
    const int warp = t >> 5;
    const int lane = t & 31;

    const uint32_t mbE = (uint32_t)__cvta_generic_to_shared(&mbar[0]);
    const uint32_t mbA = (uint32_t)__cvta_generic_to_shared(&mbar[1]);
    const uint32_t mbB = (uint32_t)__cvta_generic_to_shared(&mbar[2]);
    const uint32_t mbC = (uint32_t)__cvta_generic_to_shared(&mbar[3]);
    const uint32_t tile_a = (uint32_t)__cvta_generic_to_shared(tile);

    if (t == 0) {
        asm volatile("mbarrier.init.shared.b64 [%0], 1;" :: "r"(mbE) : "memory");
        asm volatile("mbarrier.init.shared.b64 [%0], 1;" :: "r"(mbA) : "memory");
        asm volatile("mbarrier.init.shared.b64 [%0], 1;" :: "r"(mbB) : "memory");
        asm volatile("mbarrier.init.shared.b64 [%0], 1;" :: "r"(mbC) : "memory");
        asm volatile("fence.proxy.async.shared::cta;" ::: "memory");

        unsigned long long pol;
        asm volatile("createpolicy.fractional.L2::evict_first.b64 %0, 1.0;" : "=l"(pol));

        const float* gsrc = attrs + (size_t)b * (A_NUM * D_DIM);

        // Entity row first (1KB, lands almost immediately).
        asm volatile("mbarrier.arrive.expect_tx.shared.b64 _, [%0], %1;"
                     :: "r"(mbE), "r"((uint32_t)ENT_BYTES) : "memory");
        asm volatile("cp.async.bulk.shared::cta.global.mbarrier::complete_tx::bytes"
                     ".L2::cache_hint [%0], [%1], %2, [%3], %4;"
                     :: "r"(tile_a + TILE_BYTES), "l"(ent + (size_t)b * D_DIM),
                        "r"((uint32_t)ENT_BYTES), "r"(mbE), "l"(pol) : "memory");
        // Chunk A: rows 0..19
        asm volatile("mbarrier.arrive.expect_tx.shared.b64 _, [%0], %1;"
                     :: "r"(mbA), "r"((uint32_t)CHUNKA_BYTES) : "memory");
        asm volatile("cp.async.bulk.shared::cta.global.mbarrier::complete_tx::bytes"
                     ".L2::cache_hint [%0], [%1], %2, [%3], %4;"
                     :: "r"(tile_a), "l"(gsrc),
                        "r"((uint32_t)CHUNKA_BYTES), "r"(mbA), "l"(pol) : "memory");
        // Chunk B: rows 20..39
        asm volatile("mbarrier.arrive.expect_tx.shared.b64 _, [%0], %1;"
                     :: "r"(mbB), "r"((uint32_t)CHUNKB_BYTES) : "memory");
        asm volatile("cp.async.bulk.shared::cta.global.mbarrier::complete_tx::bytes"
                     ".L2::cache_hint [%0], [%1], %2, [%3], %4;"
                     :: "r"(tile_a + BASE_B * 1024u), "l"(gsrc + BASE_B * D_DIM),
                        "r"((uint32_t)CHUNKB_BYTES), "r"(mbB), "l"(pol) : "memory");
        // Chunk C: rows 40..49
        asm volatile("mbarrier.arrive.expect_tx.shared.b64 _, [%0], %1;"
                     :: "r"(mbC), "r"((uint32_t)CHUNKC_BYTES) : "memory");
        asm volatile("cp.async.bulk.shared::cta.global.mbarrier::complete_tx::bytes"
                     ".L2::cache_hint [%0], [%1], %2, [%3], %4;"
                     :: "r"(tile_a + BASE_C * 1024u), "l"(gsrc + BASE_C * D_DIM),
                        "r"((uint32_t)CHUNKC_BYTES), "r"(mbC), "l"(pol) : "memory");
    }

    // Weight vectors (2KB, L2-resident) — overlap TMA latency.
    const float4* aa4 = reinterpret_cast<const float4*>(aa);
    const float4 aw0 = aa4[lane];            // a_attr cols 4*lane..
    const float4 aw1 = aa4[32 + lane];       // a_attr cols 128+4*lane..
    const float4 ew0 = aa4[64 + lane];       // a_ent
    const float4 ew1 = aa4[96 + lane];

    __syncthreads();   // mbarrier inits visible

#define WAIT_MB(MB)                                                             \
    asm volatile(                                                               \
        "{\n\t.reg .pred P;\n\t"                                                \
        "WL%=:\n\t"                                                             \
        "mbarrier.try_wait.parity.acquire.cta.shared::cta.b64 P, [%0], 0, 0x989680;\n\t" \
        "@P bra WD%=;\n\tbra WL%=;\n\tWD%=:\n\t}" :: "r"(MB) : "memory")

    // --- entity dot, computed redundantly by every warp (all lanes get ed) ---
    WAIT_MB(mbE);
    float ed;
    {
        const float4* e4 = reinterpret_cast<const float4*>(ents);
        const float4 ev0 = e4[lane];
        const float4 ev1 = e4[32 + lane];
        float p = ev0.x * ew0.x + ev0.y * ew0.y + ev0.z * ew0.z + ev0.w * ew0.w
                + ev1.x * ew1.x + ev1.y * ew1.y + ev1.z * ew1.z + ev1.w * ew1.w;
        p += __shfl_xor_sync(0xffffffffu, p, 16);
        p += __shfl_xor_sync(0xffffffffu, p, 8);
        p += __shfl_xor_sync(0xffffffffu, p, 4);
        p += __shfl_xor_sync(0xffffffffu, p, 2);
        p += __shfl_xor_sync(0xffffffffu, p, 1);
        ed = p;
    }

    const float4* tile4 = reinterpret_cast<const float4*>(tile);

    // Row logit -> unnormalized weight q = exp(leakyrelu(s+ed)), via lane 0.
#define ROW_Q(a)                                                                \
    do {                                                                        \
        const float4 v0 = tile4[(a) * 64 + lane];                               \
        const float4 v1 = tile4[(a) * 64 + 32 + lane];                          \
        float s = v0.x * aw0.x + v0.y * aw0.y + v0.z * aw0.z + v0.w * aw0.w     \
                + v1.x * aw1.x + v1.y * aw1.y + v1.z * aw1.z + v1.w * aw1.w;    \
        s += __shfl_xor_sync(0xffffffffu, s, 16);                               \
        s += __shfl_xor_sync(0xffffffffu, s, 8);                                \
        s += __shfl_xor_sync(0xffffffffu, s, 4);                                \
        s += __shfl_xor_sync(0xffffffffu, s, 2);                                \
        s += __shfl_xor_sync(0xffffffffu, s, 1);                                \
        if (lane == 0) {                                                        \
            float e = s + ed;                                                   \
            e = (e > 0.f) ? e : ALPHA * e;                                      \
            e_s[(a)] = __expf(e);                                               \
        }                                                                       \
    } while (0)

    // Fused weighted-sum accumulate over [lo, lo+n) — thread t owns column t.
    float acc0 = 0.f, acc1 = 0.f, qsum = 0.f;
#define WSUM_RANGE(lo, n)                                                       \
    _Pragma("unroll")                                                           \
    for (int a = (lo); a < (lo) + (n); a += 2) {                                \
        const float q0 = e_s[a];                                                \
        const float q1 = e_s[a + 1];                                            \
        acc0 = fmaf(q0, tile[a * D_DIM + t],       acc0);                       \
        acc1 = fmaf(q1, tile[(a + 1) * D_DIM + t], acc1);                       \
        qsum += q0 + q1;                                                        \
    }

    // --- chunk A: rows 0..19. warp w: rows w, w+8; warps<4: w+16 ---
    WAIT_MB(mbA);
    ROW_Q(warp);
    ROW_Q(warp + 8);
    if (warp < 4) ROW_Q(warp + 16);
    __syncthreads();           // e_s[0..19] ready
    WSUM_RANGE(0, ROWS_A)      // hidden under chunk B's stream

    // --- chunk B: rows 20..39 ---
    WAIT_MB(mbB);
    ROW_Q(BASE_B + warp);
    ROW_Q(BASE_B + warp + 8);
    if (warp < 4) ROW_Q(BASE_B + warp + 16);
    __syncthreads();           // e_s[20..39] ready
    WSUM_RANGE(BASE_B, ROWS_B) // hidden under chunk C's stream

    // --- chunk C: rows 40..49 (the only exposed tail) ---
    WAIT_MB(mbC);
    ROW_Q(BASE_C + warp);
    if (warp < 2) ROW_Q(BASE_C + warp + 8);
    __syncthreads();           // e_s[40..49] ready
    WSUM_RANGE(BASE_C, ROWS_C)

    // --- deferred normalization + streaming store ---
    __stcs(out + (size_t)b * D_DIM + t, (acc0 + acc1) * ((float)A_NUM / qsum));
#undef WAIT_MB
#undef ROW_Q
#undef WSUM_RANGE
}

extern "C" void kernel_launch(void* const* d_in, const int* in_sizes, int n_in,
                              void* d_out, int out_size)
{
    const float* attrs = (const float*)d_in[0];   // [16384, 50, 256]
    const float* ent   = (const float*)d_in[1];   // [16384, 256]
    const float* aa    = (const float*)d_in[2];   // [512, 1]
    float* out         = (float*)d_out;           // [16384, 256]

    static int attr_set = 0;
    if (!attr_set) {
        cudaFuncSetAttribute(struct_attn_kernel,
                             cudaFuncAttributeMaxDynamicSharedMemorySize, DYN_SMEM);
        attr_set = 1;
    }

    const int B = in_sizes[1] / D_DIM;            // 16384
    struct_attn_kernel<<<B, 256, DYN_SMEM>>>(attrs, ent, aa, out);
}

// round 14
// speedup vs baseline: 1.0131x; 1.0131x over previous
#include <cuda_runtime.h>
#include <cstdint>

// StructAttentionLayer: B=16384, A=50, D=256, fp32. HBM-bound (873MB, read once).
// R14 = R12 (best: 123.4us) with the chunk split shifted 26/24 -> 32/18.
// Identical wait/barrier structure (3 waits, 3 syncs — R13 proved extra
// waits cost ~2-3us each); only the exposed tail (chunk B logits+wsum)
// shrinks from 24 rows to 18.
//   q[a] = exp(leakyrelu(e[a])) (no max shift — validated rel_err ~3e-7),
//   out = (A/Σq) · Σ q[a]·attrs[a,:].

#define A_NUM 50
#define D_DIM 256
#define ALPHA 0.2f
#define ROWS_A 32
#define ROWS_B (A_NUM - ROWS_A)                 // 18
#define CHUNKA_BYTES (ROWS_A * D_DIM * 4)       // 32768
#define CHUNKB_BYTES (ROWS_B * D_DIM * 4)       // 18432
#define ENT_BYTES    (D_DIM * 4)                // 1024
#define TILE_BYTES   (A_NUM * D_DIM * 4)        // 51200
#define DYN_SMEM     (TILE_BYTES + ENT_BYTES)   // 52224

__global__ __launch_bounds__(256, 4)
void struct_attn_kernel(const float* __restrict__ attrs,
                        const float* __restrict__ ent,
                        const float* __restrict__ aa,
                        float* __restrict__ out)
{
    extern __shared__ __align__(128) float sm[];
    float* tile = sm;                          // tile[a*256 + d]
    float* ents = sm + A_NUM * D_DIM;          // ents[256]

    __shared__ float e_s[52];                  // unnormalized weights q[a]
    __shared__ __align__(8) unsigned long long mbar[3];  // [0]=ent, [1]=A, [2]=B

    const int b    = blockIdx.x;
    const int t    = threadIdx.x;
    const int warp = t >> 5;
    const int lane = t & 31;

    const uint32_t mbE = (uint32_t)__cvta_generic_to_shared(&mbar[0]);
    const uint32_t mbA = (uint32_t)__cvta_generic_to_shared(&mbar[1]);
    const uint32_t mbB = (uint32_t)__cvta_generic_to_shared(&mbar[2]);
    const uint32_t tile_a = (uint32_t)__cvta_generic_to_shared(tile);

    if (t == 0) {
        asm volatile("mbarrier.init.shared.b64 [%0], 1;" :: "r"(mbE) : "memory");
        asm volatile("mbarrier.init.shared.b64 [%0], 1;" :: "r"(mbA) : "memory");
        asm volatile("mbarrier.init.shared.b64 [%0], 1;" :: "r"(mbB) : "memory");
        asm volatile("fence.proxy.async.shared::cta;" ::: "memory");

        unsigned long long pol;
        asm volatile("createpolicy.fractional.L2::evict_first.b64 %0, 1.0;" : "=l"(pol));

        const float* gsrc = attrs + (size_t)b * (A_NUM * D_DIM);

        // Entity row first (1KB, lands almost immediately).
        asm volatile("mbarrier.arrive.expect_tx.shared.b64 _, [%0], %1;"
                     :: "r"(mbE), "r"((uint32_t)ENT_BYTES) : "memory");
        asm volatile("cp.async.bulk.shared::cta.global.mbarrier::complete_tx::bytes"
                     ".L2::cache_hint [%0], [%1], %2, [%3], %4;"
                     :: "r"(tile_a + TILE_BYTES), "l"(ent + (size_t)b * D_DIM),
                        "r"((uint32_t)ENT_BYTES), "r"(mbE), "l"(pol) : "memory");
        // Chunk A: rows 0..31
        asm volatile("mbarrier.arrive.expect_tx.shared.b64 _, [%0], %1;"
                     :: "r"(mbA), "r"((uint32_t)CHUNKA_BYTES) : "memory");
        asm volatile("cp.async.bulk.shared::cta.global.mbarrier::complete_tx::bytes"
                     ".L2::cache_hint [%0], [%1], %2, [%3], %4;"
                     :: "r"(tile_a), "l"(gsrc),
                        "r"((uint32_t)CHUNKA_BYTES), "r"(mbA), "l"(pol) : "memory");
        // Chunk B: rows 32..49
        asm volatile("mbarrier.arrive.expect_tx.shared.b64 _, [%0], %1;"
                     :: "r"(mbB), "r"((uint32_t)CHUNKB_BYTES) : "memory");
        asm volatile("cp.async.bulk.shared::cta.global.mbarrier::complete_tx::bytes"
                     ".L2::cache_hint [%0], [%1], %2, [%3], %4;"
                     :: "r"(tile_a + CHUNKA_BYTES), "l"(gsrc + ROWS_A * D_DIM),
                        "r"((uint32_t)CHUNKB_BYTES), "r"(mbB), "l"(pol) : "memory");
    }

    // Weight vectors (2KB, L2-resident) — overlap TMA latency.
    const float4* aa4 = reinterpret_cast<const float4*>(aa);
    const float4 aw0 = aa4[lane];            // a_attr cols 4*lane..
    const float4 aw1 = aa4[32 + lane];       // a_attr cols 128+4*lane..
    const float4 ew0 = aa4[64 + lane];       // a_ent
    const float4 ew1 = aa4[96 + lane];

    __syncthreads();   // mbarrier inits visible

#define WAIT_MB(MB)                                                             \
    asm volatile(                                                               \
        "{\n\t.reg .pred P;\n\t"                                                \
        "WL%=:\n\t"                                                             \
        "mbarrier.try_wait.parity.acquire.cta.shared::cta.b64 P, [%0], 0, 0x989680;\n\t" \
        "@P bra WD%=;\n\tbra WL%=;\n\tWD%=:\n\t}" :: "r"(MB) : "memory")

    // --- entity dot, computed redundantly by every warp (all lanes get ed) ---
    WAIT_MB(mbE);
    float ed;
    {
        const float4* e4 = reinterpret_cast<const float4*>(ents);
        const float4 ev0 = e4[lane];
        const float4 ev1 = e4[32 + lane];
        float p = ev0.x * ew0.x + ev0.y * ew0.y + ev0.z * ew0.z + ev0.w * ew0.w
                + ev1.x * ew1.x + ev1.y * ew1.y + ev1.z * ew1.z + ev1.w * ew1.w;
        p += __shfl_xor_sync(0xffffffffu, p, 16);
        p += __shfl_xor_sync(0xffffffffu, p, 8);
        p += __shfl_xor_sync(0xffffffffu, p, 4);
        p += __shfl_xor_sync(0xffffffffu, p, 2);
        p += __shfl_xor_sync(0xffffffffu, p, 1);
        ed = p;
    }

    const float4* tile4 = reinterpret_cast<const float4*>(tile);

    // Row logit -> unnormalized weight q = exp(leakyrelu(s+ed)), via lane 0.
#define ROW_Q(a)                                                                \
    do {                                                                        \
        const float4 v0 = tile4[(a) * 64 + lane];                               \
        const float4 v1 = tile4[(a) * 64 + 32 + lane];                          \
        float s = v0.x * aw0.x + v0.y * aw0.y + v0.z * aw0.z + v0.w * aw0.w     \
                + v1.x * aw1.x + v1.y * aw1.y + v1.z * aw1.z + v1.w * aw1.w;    \
        s += __shfl_xor_sync(0xffffffffu, s, 16);                               \
        s += __shfl_xor_sync(0xffffffffu, s, 8);                                \
        s += __shfl_xor_sync(0xffffffffu, s, 4);                                \
        s += __shfl_xor_sync(0xffffffffu, s, 2);                                \
        s += __shfl_xor_sync(0xffffffffu, s, 1);                                \
        if (lane == 0) {                                                        \
            float e = s + ed;                                                   \
            e = (e > 0.f) ? e : ALPHA * e;                                      \
            e_s[(a)] = __expf(e);                                               \
        }                                                                       \
    } while (0)

    // --- chunk A: rows 0..31. warp w: rows w, w+8, w+16, w+24 ---
    WAIT_MB(mbA);
    ROW_Q(warp);
    ROW_Q(warp + 8);
    ROW_Q(warp + 16);
    ROW_Q(warp + 24);
    __syncthreads();   // e_s[0..31] ready

    // --- chunk-A weighted sum, hidden under chunk B's stream ---
    float acc0 = 0.f, acc1 = 0.f, qsum = 0.f;
#pragma unroll
    for (int a = 0; a < ROWS_A; a += 2) {
        const float q0 = e_s[a];
        const float q1 = e_s[a + 1];
        acc0 = fmaf(q0, tile[a * D_DIM + t],       acc0);
        acc1 = fmaf(q1, tile[(a + 1) * D_DIM + t], acc1);
        qsum += q0 + q1;
    }

    // --- chunk B: rows 32..49. warp w: rows 32+w, 40+w; warps 0,1: 48+w ---
    WAIT_MB(mbB);
    ROW_Q(32 + warp);
    ROW_Q(40 + warp);
    if (warp < 2) ROW_Q(48 + warp);
    __syncthreads();   // e_s[32..49] ready

#pragma unroll
    for (int a = ROWS_A; a < A_NUM; a += 2) {
        const float q0 = e_s[a];
        const float q1 = e_s[a + 1];
        acc0 = fmaf(q0, tile[a * D_DIM + t],       acc0);
        acc1 = fmaf(q1, tile[(a + 1) * D_DIM + t], acc1);
        qsum += q0 + q1;
    }

    // --- deferred normalization + streaming store ---
    __stcs(out + (size_t)b * D_DIM + t, (acc0 + acc1) * ((float)A_NUM / qsum));
#undef WAIT_MB
#undef ROW_Q
}

extern "C" void kernel_launch(void* const* d_in, const int* in_sizes, int n_in,
                              void* d_out, int out_size)
{
    const float* attrs = (const float*)d_in[0];   // [16384, 50, 256]
    const float* ent   = (const float*)d_in[1];   // [16384, 256]
    const float* aa    = (const float*)d_in[2];   // [512, 1]
    float* out         = (float*)d_out;           // [16384, 256]

    static int attr_set = 0;
    if (!attr_set) {
        cudaFuncSetAttribute(struct_attn_kernel,
                             cudaFuncAttributeMaxDynamicSharedMemorySize, DYN_SMEM);
        attr_set = 1;
    }

    const int B = in_sizes[1] / D_DIM;            // 16384
    struct_attn_kernel<<<B, 256, DYN_SMEM>>>(attrs, ent, aa, out);
}

// round 15
// speedup vs baseline: 1.0272x; 1.0140x over previous
#include <cuda_runtime.h>
#include <cstdint>

// StructAttentionLayer: B=16384, A=50, D=256, fp32. HBM-bound (873MB, read once).
// R15: 8 SLOTS/SM streaming design. CTA = 128 threads + 27.6KB SMEM (two
// 13-row ping-pong buffers + ent row) -> 8 CTAs/SM. Deferred-normalization
// softmax lets the 50 rows STREAM through the ping-pong: per chunk
// q=exp(leakyrelu(e)) then fused weighted-sum accumulate, then refill.
// 8 independently-staggered DRAM streams/SM kill the 4-slot convoy (86% cap).

#define A_NUM 50
#define D_DIM 256
#define ALPHA 0.2f
#define CH_ROWS 13
#define BUF_FLOATS (CH_ROWS * D_DIM)            // 3328
#define BUF_BYTES  (CH_ROWS * D_DIM * 4)        // 13312
#define ENT_BYTES  (D_DIM * 4)                  // 1024
#define DYN_SMEM   (2 * BUF_BYTES + ENT_BYTES)  // 27648

__global__ __launch_bounds__(128, 8)
void struct_attn_kernel(const float* __restrict__ attrs,
                        const float* __restrict__ ent,
                        const float* __restrict__ aa,
                        float* __restrict__ out)
{
    extern __shared__ __align__(128) float sm[];
    float* buf0 = sm;                          // 13 rows
    float* buf1 = sm + BUF_FLOATS;             // 13 rows
    float* ents = sm + 2 * BUF_FLOATS;         // 256

    __shared__ float e_s[52];                  // unnormalized weights q[a]
    __shared__ __align__(8) unsigned long long mbar[3];  // [0]=ent,[1]=buf0,[2]=buf1

    const int b    = blockIdx.x;
    const int t    = threadIdx.x;              // 0..127
    const int warp = t >> 5;                   // 0..3
    const int lane = t & 31;

    const uint32_t mbE = (uint32_t)__cvta_generic_to_shared(&mbar[0]);
    const uint32_t mb0 = (uint32_t)__cvta_generic_to_shared(&mbar[1]);
    const uint32_t mb1 = (uint32_t)__cvta_generic_to_shared(&mbar[2]);
    const uint32_t buf0_a = (uint32_t)__cvta_generic_to_shared(buf0);
    const uint32_t buf1_a = (uint32_t)__cvta_generic_to_shared(buf1);

    const float* gsrc = attrs + (size_t)b * (A_NUM * D_DIM);

#define ISSUE(BUF_A, MB, SRC, BYTES)                                            \
    do {                                                                        \
        asm volatile("mbarrier.arrive.expect_tx.shared.b64 _, [%0], %1;"        \
                     :: "r"(MB), "r"((uint32_t)(BYTES)) : "memory");            \
        asm volatile("cp.async.bulk.shared::cta.global.mbarrier::complete_tx::bytes" \
                     ".L2::cache_hint [%0], [%1], %2, [%3], %4;"                \
                     :: "r"(BUF_A), "l"(SRC), "r"((uint32_t)(BYTES)), "r"(MB),  \
                        "l"(pol) : "memory");                                   \
    } while (0)

    if (t == 0) {
        asm volatile("mbarrier.init.shared.b64 [%0], 1;" :: "r"(mbE) : "memory");
        asm volatile("mbarrier.init.shared.b64 [%0], 1;" :: "r"(mb0) : "memory");
        asm volatile("mbarrier.init.shared.b64 [%0], 1;" :: "r"(mb1) : "memory");
        asm volatile("fence.proxy.async.shared::cta;" ::: "memory");

        unsigned long long pol;
        asm volatile("createpolicy.fractional.L2::evict_first.b64 %0, 1.0;" : "=l"(pol));

        ISSUE((uint32_t)__cvta_generic_to_shared(ents), mbE,
              ent + (size_t)b * D_DIM, ENT_BYTES);
        ISSUE(buf0_a, mb0, gsrc,               13 * 1024);   // rows 0..12
        ISSUE(buf1_a, mb1, gsrc + 13 * D_DIM,  13 * 1024);   // rows 13..25
    }

    // Weight vectors (2KB, L2-resident) — overlap TMA latency.
    const float4* aa4 = reinterpret_cast<const float4*>(aa);
    const float4 aw0 = aa4[lane];            // a_attr cols 4*lane..
    const float4 aw1 = aa4[32 + lane];       // a_attr cols 128+4*lane..
    const float4 ew0 = aa4[64 + lane];       // a_ent
    const float4 ew1 = aa4[96 + lane];

    __syncthreads();   // mbarrier inits visible

#define WAIT_MB(MB, PH)                                                         \
    asm volatile(                                                               \
        "{\n\t.reg .pred P;\n\t"                                                \
        "WL%=:\n\t"                                                             \
        "mbarrier.try_wait.parity.acquire.cta.shared::cta.b64 P, [%0], %1, 0x989680;\n\t" \
        "@P bra WD%=;\n\tbra WL%=;\n\tWD%=:\n\t}" :: "r"(MB), "r"((uint32_t)(PH)) : "memory")

    // --- entity dot, computed redundantly by every warp (all lanes get ed) ---
    WAIT_MB(mbE, 0);
    float ed;
    {
        const float4* e4 = reinterpret_cast<const float4*>(ents);
        const float4 ev0 = e4[lane];
        const float4 ev1 = e4[32 + lane];
        float p = ev0.x * ew0.x + ev0.y * ew0.y + ev0.z * ew0.z + ev0.w * ew0.w
                + ev1.x * ew1.x + ev1.y * ew1.y + ev1.z * ew1.z + ev1.w * ew1.w;
        p += __shfl_xor_sync(0xffffffffu, p, 16);
        p += __shfl_xor_sync(0xffffffffu, p, 8);
        p += __shfl_xor_sync(0xffffffffu, p, 4);
        p += __shfl_xor_sync(0xffffffffu, p, 2);
        p += __shfl_xor_sync(0xffffffffu, p, 1);
        ed = p;
    }

    // Local row lr of buffer bp -> q = exp(leakyrelu(s+ed)) into e_s[ga].
#define ROW_Q(bp4, lr, ga)                                                      \
    do {                                                                        \
        const float4 v0 = (bp4)[(lr) * 64 + lane];                              \
        const float4 v1 = (bp4)[(lr) * 64 + 32 + lane];                         \
        float s = v0.x * aw0.x + v0.y * aw0.y + v0.z * aw0.z + v0.w * aw0.w     \
                + v1.x * aw1.x + v1.y * aw1.y + v1.z * aw1.z + v1.w * aw1.w;    \
        s += __shfl_xor_sync(0xffffffffu, s, 16);                               \
        s += __shfl_xor_sync(0xffffffffu, s, 8);                                \
        s += __shfl_xor_sync(0xffffffffu, s, 4);                                \
        s += __shfl_xor_sync(0xffffffffu, s, 2);                                \
        s += __shfl_xor_sync(0xffffffffu, s, 1);                                \
        if (lane == 0) {                                                        \
            float e = s + ed;                                                   \
            e = (e > 0.f) ? e : ALPHA * e;                                      \
            e_s[(ga)] = __expf(e);                                              \
        }                                                                       \
    } while (0)

    float acc0 = 0.f, acc1 = 0.f, qsum = 0.f;

    // 4 chunks: rows {0..12}->buf0, {13..25}->buf1, {26..38}->buf0, {39..49}->buf1
#pragma unroll
    for (int c = 0; c < 4; c++) {
        const int base = c * 13;
        const int rows = (c == 3) ? 11 : 13;
        float* bp = (c & 1) ? buf1 : buf0;
        const float4* bp4 = reinterpret_cast<const float4*>(bp);
        const uint32_t mb = (c & 1) ? mb1 : mb0;

        WAIT_MB(mb, c >> 1);   // phase 0 for chunks 0/1, phase 1 for 2/3

        // logits: warp w -> local rows w, w+4, w+8; extras for rows 12 / 10.
        ROW_Q(bp4, warp,     base + warp);
        ROW_Q(bp4, warp + 4, base + warp + 4);
        if (c < 3) {
            ROW_Q(bp4, warp + 8, base + warp + 8);
            if (warp == 0) ROW_Q(bp4, 12, base + 12);
        } else {
            if (warp < 3) ROW_Q(bp4, warp + 8, base + warp + 8);
        }
        __syncthreads();   // e_s[base..base+rows) ready

        // fused weighted sum: thread t owns columns t and t+128
        for (int i = 0; i < rows; i++) {
            const float q = e_s[base + i];
            acc0 = fmaf(q, bp[i * D_DIM + t],       acc0);
            acc1 = fmaf(q, bp[i * D_DIM + 128 + t], acc1);
            qsum += q;
        }

        if (c < 2) {
            __syncthreads();   // buffer fully consumed by ALL warps
            if (t == 0) {
                unsigned long long pol;
                asm volatile("createpolicy.fractional.L2::evict_first.b64 %0, 1.0;"
                             : "=l"(pol));
                if (c == 0)
                    ISSUE(buf0_a, mb0, gsrc + 26 * D_DIM, 13 * 1024);  // rows 26..38
                else
                    ISSUE(buf1_a, mb1, gsrc + 39 * D_DIM, 11 * 1024);  // rows 39..49
            }
        }
    }

    // --- deferred normalization + streaming store (cols t, t+128) ---
    const float scale = (float)A_NUM / qsum;
    __stcs(out + (size_t)b * D_DIM + t,       acc0 * scale);
    __stcs(out + (size_t)b * D_DIM + 128 + t, acc1 * scale);
#undef WAIT_MB
#undef ROW_Q
#undef ISSUE
}

extern "C" void kernel_launch(void* const* d_in, const int* in_sizes, int n_in,
                              void* d_out, int out_size)
{
    const float* attrs = (const float*)d_in[0];   // [16384, 50, 256]
    const float* ent   = (const float*)d_in[1];   // [16384, 256]
    const float* aa    = (const float*)d_in[2];   // [512, 1]
    float* out         = (float*)d_out;           // [16384, 256]

    static int attr_set = 0;
    if (!attr_set) {
        cudaFuncSetAttribute(struct_attn_kernel,
                             cudaFuncAttributeMaxDynamicSharedMemorySize, DYN_SMEM);
        attr_set = 1;
    }

    const int B = in_sizes[1] / D_DIM;            // 16384
    struct_attn_kernel<<<B, 128, DYN_SMEM>>>(attrs, ent, aa, out);
}

// round 16
// speedup vs baseline: 1.0296x; 1.0023x over previous
#include <cuda_runtime.h>
#include <cstdint>

// StructAttentionLayer: B=16384, A=50, D=256, fp32. HBM-bound (873MB, read once).
// R16: 8 slots/SM (128thr, 27.6KB SMEM ping-pong) + SINGLE-READ FUSION:
// after the logit dot's xor-shuffle reduce every lane holds s, so q =
// exp(leakyrelu(s+ed)) is computed per-lane and fused straight into per-lane
// output accumulators from the SAME v0/v1 registers. Tile crosses the SMEM
// port ONCE; no e_s; ZERO intra-chunk CTA syncs (warps decoupled; refills
// gated by two count-4 mbarriers). Epilogue: 4-warp combine in buf0's dead
// space. Deferred normalization: out = (A/Σq)·Σ q·row (rel_err ~3e-7).

#define A_NUM 50
#define D_DIM 256
#define ALPHA 0.2f
#define CH 13
#define BUF_FLOATS (CH * D_DIM)                 // 3328
#define BUF_BYTES  (CH * D_DIM * 4)             // 13312
#define ENT_BYTES  (D_DIM * 4)                  // 1024
#define DYN_SMEM   (2 * BUF_BYTES + ENT_BYTES)  // 27648

__global__ __launch_bounds__(128, 8)
void struct_attn_kernel(const float* __restrict__ attrs,
                        const float* __restrict__ ent,
                        const float* __restrict__ aa,
                        float* __restrict__ out)
{
    extern __shared__ __align__(128) float sm[];
    float* buf0 = sm;                          // 13 rows; reused as part[] at end
    float* buf1 = sm + BUF_FLOATS;             // 13 rows
    float* ents = sm + 2 * BUF_FLOATS;         // 256

    __shared__ float qs[4];
    __shared__ __align__(8) unsigned long long mbar[5]; // E, b0, b1, R0, R1

    const int b    = blockIdx.x;
    const int t    = threadIdx.x;              // 0..127
    const int warp = t >> 5;                   // 0..3
    const int lane = t & 31;

    const uint32_t mbE  = (uint32_t)__cvta_generic_to_shared(&mbar[0]);
    const uint32_t mb0  = (uint32_t)__cvta_generic_to_shared(&mbar[1]);
    const uint32_t mb1  = (uint32_t)__cvta_generic_to_shared(&mbar[2]);
    const uint32_t mbR0 = (uint32_t)__cvta_generic_to_shared(&mbar[3]);
    const uint32_t mbR1 = (uint32_t)__cvta_generic_to_shared(&mbar[4]);
    const uint32_t buf0_a = (uint32_t)__cvta_generic_to_shared(buf0);
    const uint32_t buf1_a = (uint32_t)__cvta_generic_to_shared(buf1);

    const float* gsrc = attrs + (size_t)b * (A_NUM * D_DIM);

#define ISSUE(BUF_A, MB, SRC, BYTES)                                            \
    do {                                                                        \
        unsigned long long pol;                                                 \
        asm volatile("createpolicy.fractional.L2::evict_first.b64 %0, 1.0;"     \
                     : "=l"(pol));                                              \
        asm volatile("mbarrier.arrive.expect_tx.shared.b64 _, [%0], %1;"        \
                     :: "r"(MB), "r"((uint32_t)(BYTES)) : "memory");            \
        asm volatile("cp.async.bulk.shared::cta.global.mbarrier::complete_tx::bytes" \
                     ".L2::cache_hint [%0], [%1], %2, [%3], %4;"                \
                     :: "r"(BUF_A), "l"(SRC), "r"((uint32_t)(BYTES)), "r"(MB),  \
                        "l"(pol) : "memory");                                   \
    } while (0)

    if (t == 0) {
        asm volatile("mbarrier.init.shared.b64 [%0], 1;" :: "r"(mbE)  : "memory");
        asm volatile("mbarrier.init.shared.b64 [%0], 1;" :: "r"(mb0)  : "memory");
        asm volatile("mbarrier.init.shared.b64 [%0], 1;" :: "r"(mb1)  : "memory");
        asm volatile("mbarrier.init.shared.b64 [%0], 4;" :: "r"(mbR0) : "memory");
        asm volatile("mbarrier.init.shared.b64 [%0], 4;" :: "r"(mbR1) : "memory");
        asm volatile("fence.proxy.async.shared::cta;" ::: "memory");

        ISSUE((uint32_t)__cvta_generic_to_shared(ents), mbE,
              ent + (size_t)b * D_DIM, ENT_BYTES);
        ISSUE(buf0_a, mb0, gsrc,              13 * 1024);   // rows 0..12
        ISSUE(buf1_a, mb1, gsrc + 13 * D_DIM, 13 * 1024);   // rows 13..25
    }

    // Weight vectors (2KB, L2-resident) — overlap TMA latency.
    const float4* aa4 = reinterpret_cast<const float4*>(aa);
    const float4 aw0 = aa4[lane];            // a_attr cols 4*lane..
    const float4 aw1 = aa4[32 + lane];       // a_attr cols 128+4*lane..
    const float4 ew0 = aa4[64 + lane];       // a_ent
    const float4 ew1 = aa4[96 + lane];

    __syncthreads();   // mbarrier inits visible

#define WAIT_MB(MB, PH)                                                         \
    asm volatile(                                                               \
        "{\n\t.reg .pred P;\n\t"                                                \
        "WL%=:\n\t"                                                             \
        "mbarrier.try_wait.parity.acquire.cta.shared::cta.b64 P, [%0], %1, 0x989680;\n\t" \
        "@P bra WD%=;\n\tbra WL%=;\n\tWD%=:\n\t}" :: "r"(MB), "r"((uint32_t)(PH)) : "memory")

    // --- entity dot (redundant per warp; xor-reduce leaves ed in all lanes) ---
    WAIT_MB(mbE, 0);
    float ed;
    {
        const float4* e4 = reinterpret_cast<const float4*>(ents);
        const float4 ev0 = e4[lane];
        const float4 ev1 = e4[32 + lane];
        float p = ev0.x * ew0.x + ev0.y * ew0.y + ev0.z * ew0.z + ev0.w * ew0.w
                + ev1.x * ew1.x + ev1.y * ew1.y + ev1.z * ew1.z + ev1.w * ew1.w;
        p += __shfl_xor_sync(0xffffffffu, p, 16);
        p += __shfl_xor_sync(0xffffffffu, p, 8);
        p += __shfl_xor_sync(0xffffffffu, p, 4);
        p += __shfl_xor_sync(0xffffffffu, p, 2);
        p += __shfl_xor_sync(0xffffffffu, p, 1);
        ed = p;
    }

    float4 acc0 = make_float4(0.f, 0.f, 0.f, 0.f);   // cols 4*lane..
    float4 acc1 = make_float4(0.f, 0.f, 0.f, 0.f);   // cols 128+4*lane..
    float qsw = 0.f;

    // Single-read fused row: load once, dot, all-lane reduce, q, wsum FMA.
#define DO_ROW(bp4, lr)                                                         \
    do {                                                                        \
        const float4 v0 = (bp4)[(lr) * 64 + lane];                              \
        const float4 v1 = (bp4)[(lr) * 64 + 32 + lane];                         \
        float s = v0.x * aw0.x + v0.y * aw0.y + v0.z * aw0.z + v0.w * aw0.w     \
                + v1.x * aw1.x + v1.y * aw1.y + v1.z * aw1.z + v1.w * aw1.w;    \
        s += __shfl_xor_sync(0xffffffffu, s, 16);                               \
        s += __shfl_xor_sync(0xffffffffu, s, 8);                                \
        s += __shfl_xor_sync(0xffffffffu, s, 4);                                \
        s += __shfl_xor_sync(0xffffffffu, s, 2);                                \
        s += __shfl_xor_sync(0xffffffffu, s, 1);                                \
        float e = s + ed;                                                       \
        e = (e > 0.f) ? e : ALPHA * e;                                          \
        const float q = __expf(e);                                              \
        qsw += q;                                                               \
        acc0.x = fmaf(q, v0.x, acc0.x);                                         \
        acc0.y = fmaf(q, v0.y, acc0.y);                                         \
        acc0.z = fmaf(q, v0.z, acc0.z);                                         \
        acc0.w = fmaf(q, v0.w, acc0.w);                                         \
        acc1.x = fmaf(q, v1.x, acc1.x);                                         \
        acc1.y = fmaf(q, v1.y, acc1.y);                                         \
        acc1.z = fmaf(q, v1.z, acc1.z);                                         \
        acc1.w = fmaf(q, v1.w, acc1.w);                                         \
    } while (0)

    // chunks: {0..12}->buf0, {13..25}->buf1, {26..38}->buf0, {39..49}->buf1
#pragma unroll
    for (int c = 0; c < 4; c++) {
        const float4* bp4 = reinterpret_cast<const float4*>((c & 1) ? buf1 : buf0);
        WAIT_MB((c & 1) ? mb1 : mb0, c >> 1);

        DO_ROW(bp4, warp);       // local rows: w, w+4, (w+8), (12 -> warp 0)
        DO_ROW(bp4, warp + 4);
        if (c < 3) {
            DO_ROW(bp4, warp + 8);
            if (warp == 0) DO_ROW(bp4, 12);
        } else {
            if (warp < 3) DO_ROW(bp4, warp + 8);
        }

        // Refill gating: warp-leader arrives when this warp is done with the
        // buffer; t0 waits for all 4 then issues. Warps stay decoupled.
        if (c == 0) {
            __syncwarp();
            if (lane == 0)
                asm volatile("mbarrier.arrive.shared.b64 _, [%0];" :: "r"(mbR0) : "memory");
            if (t == 0) {
                WAIT_MB(mbR0, 0);
                ISSUE(buf0_a, mb0, gsrc + 26 * D_DIM, 13 * 1024);   // rows 26..38
            }
        } else if (c == 1) {
            __syncwarp();
            if (lane == 0)
                asm volatile("mbarrier.arrive.shared.b64 _, [%0];" :: "r"(mbR1) : "memory");
            if (t == 0) {
                WAIT_MB(mbR1, 0);
                ISSUE(buf1_a, mb1, gsrc + 39 * D_DIM, 11 * 1024);   // rows 39..49
            }
        }
    }

    // --- epilogue: combine 4 warp partials (reuse buf0's dead space) ---
    __syncthreads();   // all buffer reads complete before part[] overwrites buf0
    float4* part4 = reinterpret_cast<float4*>(buf0);
    part4[warp * 64 + lane]      = acc0;   // slot s -> cols 4s..4s+3
    part4[warp * 64 + 32 + lane] = acc1;   // slot 32+lane -> cols 128+4*lane..
    if (lane == 0) qs[warp] = qsw;
    __syncthreads();

    if (t < 64) {
        const float4 r0 = part4[t];
        const float4 r1 = part4[64 + t];
        const float4 r2 = part4[128 + t];
        const float4 r3 = part4[192 + t];
        const float scale = (float)A_NUM / ((qs[0] + qs[1]) + (qs[2] + qs[3]));
        float4 r;
        r.x = ((r0.x + r1.x) + (r2.x + r3.x)) * scale;
        r.y = ((r0.y + r1.y) + (r2.y + r3.y)) * scale;
        r.z = ((r0.z + r1.z) + (r2.z + r3.z)) * scale;
        r.w = ((r0.w + r1.w) + (r2.w + r3.w)) * scale;
        __stcs(reinterpret_cast<float4*>(out + (size_t)b * D_DIM) + t, r);
    }
#undef WAIT_MB
#undef DO_ROW
#undef ISSUE
}

extern "C" void kernel_launch(void* const* d_in, const int* in_sizes, int n_in,
                              void* d_out, int out_size)
{
    const float* attrs = (const float*)d_in[0];   // [16384, 50, 256]
    const float* ent   = (const float*)d_in[1];   // [16384, 256]
    const float* aa    = (const float*)d_in[2];   // [512, 1]
    float* out         = (float*)d_out;           // [16384, 256]

    static int attr_set = 0;
    if (!attr_set) {
        cudaFuncSetAttribute(struct_attn_kernel,
                             cudaFuncAttributeMaxDynamicSharedMemorySize, DYN_SMEM);
        attr_set = 1;
    }

    const int B = in_sizes[1] / D_DIM;            // 16384
    struct_attn_kernel<<<B, 128, DYN_SMEM>>>(attrs, ent, aa, out);
}

// round 17
// speedup vs baseline: 1.0367x; 1.0069x over previous
#include <cuda_runtime.h>
#include <cstdint>

// StructAttentionLayer: B=16384, A=50, D=256, fp32. HBM-bound (873MB, read once).
// R17 = R16 (8 slots/SM, single-read fusion, warp-decoupled) with a DEPTH-3
// buffer rotation: 6 chunks (9/9/9/9/9/5 rows) through 3 rotating 9-row
// buffers (same 27648B footprint -> still 8 CTAs/SM). While chunk c computes,
// c+1 and c+2 are in flight. Entity row via direct LDG (no TMA round-trip).
// Deferred normalization: out = (A/Σq)·Σ q·row, q = exp(leakyrelu(s+ed)).

#define A_NUM 50
#define D_DIM 256
#define ALPHA 0.2f
#define CH 9
#define BUF_FLOATS (CH * D_DIM)                 // 2304
#define BUF_BYTES  (CH * D_DIM * 4)             // 9216
#define DYN_SMEM   (3 * BUF_BYTES)              // 27648

__global__ __launch_bounds__(128, 8)
void struct_attn_kernel(const float* __restrict__ attrs,
                        const float* __restrict__ ent,
                        const float* __restrict__ aa,
                        float* __restrict__ out)
{
    extern __shared__ __align__(128) float sm[];
    // 3 rotating 9-row buffers; buf0 reused as part[] in the epilogue.

    __shared__ float qs[4];
    __shared__ __align__(8) unsigned long long mbar[6]; // d0,d1,d2, R0,R1,R2

    const int b    = blockIdx.x;
    const int t    = threadIdx.x;              // 0..127
    const int warp = t >> 5;                   // 0..3
    const int lane = t & 31;

    uint32_t mbD[3], mbR[3], bufA[3];
#pragma unroll
    for (int i = 0; i < 3; i++) {
        mbD[i]  = (uint32_t)__cvta_generic_to_shared(&mbar[i]);
        mbR[i]  = (uint32_t)__cvta_generic_to_shared(&mbar[3 + i]);
        bufA[i] = (uint32_t)__cvta_generic_to_shared(sm + i * BUF_FLOATS);
    }

    const float* gsrc = attrs + (size_t)b * (A_NUM * D_DIM);

#define ISSUE(BUF_A, MB, SRC, BYTES)                                            \
    do {                                                                        \
        unsigned long long pol;                                                 \
        asm volatile("createpolicy.fractional.L2::evict_first.b64 %0, 1.0;"     \
                     : "=l"(pol));                                              \
        asm volatile("mbarrier.arrive.expect_tx.shared.b64 _, [%0], %1;"        \
                     :: "r"(MB), "r"((uint32_t)(BYTES)) : "memory");            \
        asm volatile("cp.async.bulk.shared::cta.global.mbarrier::complete_tx::bytes" \
                     ".L2::cache_hint [%0], [%1], %2, [%3], %4;"                \
                     :: "r"(BUF_A), "l"(SRC), "r"((uint32_t)(BYTES)), "r"(MB),  \
                        "l"(pol) : "memory");                                   \
    } while (0)

    if (t == 0) {
#pragma unroll
        for (int i = 0; i < 3; i++) {
            asm volatile("mbarrier.init.shared.b64 [%0], 1;" :: "r"(mbD[i]) : "memory");
            asm volatile("mbarrier.init.shared.b64 [%0], 4;" :: "r"(mbR[i]) : "memory");
        }
        asm volatile("fence.proxy.async.shared::cta;" ::: "memory");
        // Prefetch chunks 0,1,2 (rows 0..8, 9..17, 18..26).
        ISSUE(bufA[0], mbD[0], gsrc,               CH * 1024);
        ISSUE(bufA[1], mbD[1], gsrc + 9  * D_DIM,  CH * 1024);
        ISSUE(bufA[2], mbD[2], gsrc + 18 * D_DIM,  CH * 1024);
    }

    // Weight vectors (2KB, L2-resident) — overlap TMA latency.
    const float4* aa4 = reinterpret_cast<const float4*>(aa);
    const float4 aw0 = aa4[lane];            // a_attr cols 4*lane..
    const float4 aw1 = aa4[32 + lane];       // a_attr cols 128+4*lane..
    const float4 ew0 = aa4[64 + lane];       // a_ent
    const float4 ew1 = aa4[96 + lane];

    // --- entity dot via direct LDG (per-warp redundant; overlaps TMA wait) ---
    float ed;
    {
        const float4* e4 = reinterpret_cast<const float4*>(ent + (size_t)b * D_DIM);
        const float4 ev0 = e4[lane];
        const float4 ev1 = e4[32 + lane];
        float p = ev0.x * ew0.x + ev0.y * ew0.y + ev0.z * ew0.z + ev0.w * ew0.w
                + ev1.x * ew1.x + ev1.y * ew1.y + ev1.z * ew1.z + ev1.w * ew1.w;
        p += __shfl_xor_sync(0xffffffffu, p, 16);
        p += __shfl_xor_sync(0xffffffffu, p, 8);
        p += __shfl_xor_sync(0xffffffffu, p, 4);
        p += __shfl_xor_sync(0xffffffffu, p, 2);
        p += __shfl_xor_sync(0xffffffffu, p, 1);
        ed = p;
    }

    __syncthreads();   // mbarrier inits visible before any try_wait

#define WAIT_MB(MB, PH)                                                         \
    asm volatile(                                                               \
        "{\n\t.reg .pred P;\n\t"                                                \
        "WL%=:\n\t"                                                             \
        "mbarrier.try_wait.parity.acquire.cta.shared::cta.b64 P, [%0], %1, 0x989680;\n\t" \
        "@P bra WD%=;\n\tbra WL%=;\n\tWD%=:\n\t}" :: "r"(MB), "r"((uint32_t)(PH)) : "memory")

    float4 acc0 = make_float4(0.f, 0.f, 0.f, 0.f);   // cols 4*lane..
    float4 acc1 = make_float4(0.f, 0.f, 0.f, 0.f);   // cols 128+4*lane..
    float qsw = 0.f;

    // Single-read fused row: load once, dot, all-lane reduce, q, wsum FMA.
#define DO_ROW(bp4, lr)                                                         \
    do {                                                                        \
        const float4 v0 = (bp4)[(lr) * 64 + lane];                              \
        const float4 v1 = (bp4)[(lr) * 64 + 32 + lane];                         \
        float s = v0.x * aw0.x + v0.y * aw0.y + v0.z * aw0.z + v0.w * aw0.w     \
                + v1.x * aw1.x + v1.y * aw1.y + v1.z * aw1.z + v1.w * aw1.w;    \
        s += __shfl_xor_sync(0xffffffffu, s, 16);                               \
        s += __shfl_xor_sync(0xffffffffu, s, 8);                                \
        s += __shfl_xor_sync(0xffffffffu, s, 4);                                \
        s += __shfl_xor_sync(0xffffffffu, s, 2);                                \
        s += __shfl_xor_sync(0xffffffffu, s, 1);                                \
        float e = s + ed;                                                       \
        e = (e > 0.f) ? e : ALPHA * e;                                          \
        const float q = __expf(e);                                              \
        qsw += q;                                                               \
        acc0.x = fmaf(q, v0.x, acc0.x);                                         \
        acc0.y = fmaf(q, v0.y, acc0.y);                                         \
        acc0.z = fmaf(q, v0.z, acc0.z);                                         \
        acc0.w = fmaf(q, v0.w, acc0.w);                                         \
        acc1.x = fmaf(q, v1.x, acc1.x);                                         \
        acc1.y = fmaf(q, v1.y, acc1.y);                                         \
        acc1.z = fmaf(q, v1.z, acc1.z);                                         \
        acc1.w = fmaf(q, v1.w, acc1.w);                                         \
    } while (0)

    // Chunks c=0..5: rows 9c..9c+8 (c<5) or 45..49 (c=5); buffer c%3,
    // phase c/3. Warp w handles local rows w, w+4, and (warp0) row 8 / 4.
#pragma unroll
    for (int c = 0; c < 6; c++) {
        const int p = c % 3;
        const float4* bp4 = reinterpret_cast<const float4*>(sm + p * BUF_FLOATS);
        WAIT_MB(mbD[p], c / 3);

        DO_ROW(bp4, warp);
        if (c < 5) {
            DO_ROW(bp4, warp + 4);
            if (warp == 0) DO_ROW(bp4, 8);
        } else {
            if (warp == 0) DO_ROW(bp4, 4);
        }

        // Refill chunk c+3 into this buffer once all 4 warps are done with it.
        if (c < 3) {
            __syncwarp();
            if (lane == 0)
                asm volatile("mbarrier.arrive.shared.b64 _, [%0];" :: "r"(mbR[p]) : "memory");
            if (t == 0) {
                WAIT_MB(mbR[p], 0);
                const int cn = c + 3;
                const uint32_t bytes = (cn == 5) ? 5 * 1024 : CH * 1024;
                ISSUE(bufA[p], mbD[p], gsrc + cn * 9 * D_DIM, bytes);
            }
        }
    }

    // --- epilogue: combine 4 warp partials (reuse buf0's dead space) ---
    __syncthreads();   // all buffer reads complete before part[] overwrites buf0
    float4* part4 = reinterpret_cast<float4*>(sm);
    part4[warp * 64 + lane]      = acc0;
    part4[warp * 64 + 32 + lane] = acc1;
    if (lane == 0) qs[warp] = qsw;
    __syncthreads();

    if (t < 64) {
        const float4 r0 = part4[t];
        const float4 r1 = part4[64 + t];
        const float4 r2 = part4[128 + t];
        const float4 r3 = part4[192 + t];
        const float scale = (float)A_NUM / ((qs[0] + qs[1]) + (qs[2] + qs[3]));
        float4 r;
        r.x = ((r0.x + r1.x) + (r2.x + r3.x)) * scale;
        r.y = ((r0.y + r1.y) + (r2.y + r3.y)) * scale;
        r.z = ((r0.z + r1.z) + (r2.z + r3.z)) * scale;
        r.w = ((r0.w + r1.w) + (r2.w + r3.w)) * scale;
        __stcs(reinterpret_cast<float4*>(out + (size_t)b * D_DIM) + t, r);
    }
#undef WAIT_MB
#undef DO_ROW
#undef ISSUE
}

extern "C" void kernel_launch(void* const* d_in, const int* in_sizes, int n_in,
                              void* d_out, int out_size)
{
    const float* attrs = (const float*)d_in[0];   // [16384, 50, 256]
    const float* ent   = (const float*)d_in[1];   // [16384, 256]
    const float* aa    = (const float*)d_in[2];   // [512, 1]
    float* out         = (float*)d_out;           // [16384, 256]

    static int attr_set = 0;
    if (!attr_set) {
        cudaFuncSetAttribute(struct_attn_kernel,
                             cudaFuncAttributeMaxDynamicSharedMemorySize, DYN_SMEM);
        attr_set = 1;
    }

    const int B = in_sizes[1] / D_DIM;            // 16384
    struct_attn_kernel<<<B, 128, DYN_SMEM>>>(attrs, ent, aa, out);
}